// round 9
// baseline (speedup 1.0000x reference)
#include <cuda_runtime.h>
#include <cstdint>

#define BB 64
#define CC 512
#define HWHW 1024
#define NN 4
#define DD 128
#define KK 1024
// P = 65536 points

// -------- scratch --------
__device__ __align__(16) float  d_eNorm[NN * KK];
__device__ __align__(16) float  d_embedT[(size_t)NN * KK * DD];   // fp32 [n][k][d] for epi gather
__device__ __align__(16) float2 d_eHL[(size_t)NN * DD * KK];      // {tf32 hi, tf32 lo} [n][d][k]
__device__ int   d_idxBuf[BB * NN * HWHW];
__device__ int   d_counts[NN * KK];
__device__ __align__(16) float d_diffPartial[8192];

__device__ __forceinline__ uint32_t f2tf32(float f) {
    uint32_t u;
    asm("cvt.rna.tf32.f32 %0, %1;" : "=r"(u) : "f"(f));
    return u;
}

// legacy warp-level tensor mma (sm_80+, plain target)
__device__ __forceinline__ void mma8(float* c, const uint32_t* a, uint32_t b0, uint32_t b1) {
    asm volatile(
        "mma.sync.aligned.m16n8k8.row.col.f32.tf32.tf32.f32 "
        "{%0,%1,%2,%3}, {%4,%5,%6,%7}, {%8,%9}, {%0,%1,%2,%3};"
        : "+f"(c[0]), "+f"(c[1]), "+f"(c[2]), "+f"(c[3])
        : "r"(a[0]), "r"(a[1]), "r"(a[2]), "r"(a[3]), "r"(b0), "r"(b1));
}

// ============================================================
// Kernel A: eNorm + embedT + packed tf32 hi/lo split + zero counts
// grid 32 (n*8+kc), 128 thr
// ============================================================
__global__ void prep_kernel(const float* __restrict__ embed) {
    const int n  = blockIdx.x >> 3;
    const int kc = blockIdx.x & 7;
    const int k  = kc * 128 + threadIdx.x;
    const float* e = embed + (size_t)n * DD * KK + k;
    float* tB = d_embedT + ((size_t)(n * KK + k)) * DD;
    float s = 0.f;
#pragma unroll 4
    for (int d = 0; d < DD; d++) {
        float v = e[(size_t)d * KK];
        s = fmaf(v, v, s);
        tB[d] = v;
        uint32_t uh = f2tf32(v);
        float fh = __uint_as_float(uh);
        float fl = __uint_as_float(f2tf32(v - fh));
        d_eHL[(size_t)(n * DD + d) * KK + k] = make_float2(fh, fl);
    }
    d_eNorm[n * KK + k] = s;
    d_counts[blockIdx.x * 128 + threadIdx.x] = 0;
}

// ============================================================
// Kernel B: tf32 3-split mma.sync distance GEMM, zero in-loop cvt
// grid (512, 4): 128 pt x 1024 codes/block, 256 thr (8 warps)
// 16 chunks of 64 codes; warp grid 4(pt) x 2(cd); warp tile 32x32
// zs2: float2[128k][132] (stride 132 f2, ==4 mod 16 -> conflict-free LDS.64)
// es2: float2[128k][68]
// ============================================================
#define ZSTR2 132
#define ESTR2 68
#define ZS2_F2  0
#define ES2_F2  16896            // 128*132
#define SM_EN_B 204800           // bytes: (16896+8704)*8
#define SM_TOTAL_B 208896        // + 1024 floats eN

__global__ __launch_bounds__(256, 1)
void vq_mma(const float* __restrict__ x, float* __restrict__ argmin_out) {
    extern __shared__ float2 sm2[];
    float2* zs2 = sm2;                    // [128 k][132]
    float2* es2 = sm2 + ES2_F2;           // [128 k][68]
    float*  eNs = (float*)((char*)sm2 + SM_EN_B);   // [1024]

    const int tid = threadIdx.x;
    const int wid = tid >> 5;
    const int lane = tid & 31;
    const int g = lane >> 2;             // 0..7
    const int t = lane & 3;              // 0..3
    const int b = blockIdx.x >> 3;
    const int hw0 = (blockIdx.x & 7) * 128;
    const int n = blockIdx.y;
    const int ptb = (wid >> 1) * 32;     // warp point base
    const int cdw = (wid & 1) * 32;      // warp code base within chunk

    // ---- stage z tile once, pre-split to tf32 hi/lo
    const float* xblk = x + ((size_t)b * CC + n * DD) * HWHW + hw0;
#pragma unroll
    for (int r = 0; r < 16; r++) {
        int l = r * 256 + tid;
        int d = l >> 5, q = l & 31;          // 32 float4 per 128-float row
        float4 v = __ldg((const float4*)(xblk + (size_t)d * HWHW) + q);
        float2* dst = zs2 + d * ZSTR2 + q * 4;
        uint32_t h;
        h = f2tf32(v.x); dst[0] = make_float2(__uint_as_float(h), __uint_as_float(f2tf32(v.x - __uint_as_float(h))));
        h = f2tf32(v.y); dst[1] = make_float2(__uint_as_float(h), __uint_as_float(f2tf32(v.y - __uint_as_float(h))));
        h = f2tf32(v.z); dst[2] = make_float2(__uint_as_float(h), __uint_as_float(f2tf32(v.z - __uint_as_float(h))));
        h = f2tf32(v.w); dst[3] = make_float2(__uint_as_float(h), __uint_as_float(f2tf32(v.w - __uint_as_float(h))));
    }
    // ---- stage all eNorm once
    ((float4*)eNs)[tid] = __ldg((const float4*)(d_eNorm + n * KK) + tid);

    float best[4] = {3.4e38f, 3.4e38f, 3.4e38f, 3.4e38f};
    int   bk[4]   = {0, 0, 0, 0};

    const float2* ehl = d_eHL + (size_t)n * DD * KK;

    for (int c = 0; c < 16; c++) {
        __syncthreads();     // prior chunk's reads done (covers zs2/eN staging on c=0)
        // ---- stage e chunk (pre-split pairs, straight copy)
#pragma unroll
        for (int r = 0; r < 16; r++) {
            int l = r * 256 + tid;           // 4096 float4 (=2 float2) transfers
            int d = l >> 5, cq = l & 31;     // 32 float4 per 64-float2 row
            float4 v = __ldg((const float4*)(ehl + (size_t)d * KK + c * 64) + cq);
            *(float4*)(es2 + d * ESTR2 + cq * 2) = v;
        }
        __syncthreads();

        float acc[2][4][4];
#pragma unroll
        for (int mf = 0; mf < 2; mf++)
#pragma unroll
            for (int nf = 0; nf < 4; nf++)
#pragma unroll
                for (int i = 0; i < 4; i++) acc[mf][nf][i] = 0.f;

#pragma unroll 4
        for (int ks = 0; ks < 16; ks++) {
            // A fragments: a0=(pt g, k t) a1=(g+8, t) a2=(g, t+4) a3=(g+8, t+4)
            const float2* zr0 = zs2 + (ks * 8 + t) * ZSTR2 + ptb + g;
            const float2* zr4 = zr0 + 4 * ZSTR2;
            uint32_t ah[2][4], al[2][4];
#pragma unroll
            for (int mf = 0; mf < 2; mf++) {
                const int o = mf * 16;
                float2 p0 = zr0[o], p1 = zr0[o + 8], p2 = zr4[o], p3 = zr4[o + 8];
                ah[mf][0] = __float_as_uint(p0.x); al[mf][0] = __float_as_uint(p0.y);
                ah[mf][1] = __float_as_uint(p1.x); al[mf][1] = __float_as_uint(p1.y);
                ah[mf][2] = __float_as_uint(p2.x); al[mf][2] = __float_as_uint(p2.y);
                ah[mf][3] = __float_as_uint(p3.x); al[mf][3] = __float_as_uint(p3.y);
            }
            // B fragments: b0=(k t, cd g) b1=(k t+4, cd g)
            const float2* er0 = es2 + (ks * 8 + t) * ESTR2 + cdw + g;
            const float2* er4 = er0 + 4 * ESTR2;
            uint32_t bh0[4], bl0[4], bh1[4], bl1[4];
#pragma unroll
            for (int nf = 0; nf < 4; nf++) {
                float2 q0 = er0[nf * 8], q1 = er4[nf * 8];
                bh0[nf] = __float_as_uint(q0.x); bl0[nf] = __float_as_uint(q0.y);
                bh1[nf] = __float_as_uint(q1.x); bl1[nf] = __float_as_uint(q1.y);
            }
            // term-outer issue: 8 independent accs between dependent repeats
#pragma unroll
            for (int mf = 0; mf < 2; mf++)
#pragma unroll
                for (int nf = 0; nf < 4; nf++)
                    mma8(acc[mf][nf], ah[mf], bh0[nf], bh1[nf]);   // hi*hi
#pragma unroll
            for (int mf = 0; mf < 2; mf++)
#pragma unroll
                for (int nf = 0; nf < 4; nf++)
                    mma8(acc[mf][nf], al[mf], bh0[nf], bh1[nf]);   // lo*hi
#pragma unroll
            for (int mf = 0; mf < 2; mf++)
#pragma unroll
                for (int nf = 0; nf < 4; nf++)
                    mma8(acc[mf][nf], ah[mf], bl0[nf], bl1[nf]);   // hi*lo
        }

        // ---- fold chunk into running argmin
        // C frag: c0=(g,2t) c1=(g,2t+1) c2=(g+8,2t) c3=(g+8,2t+1)
#pragma unroll
        for (int nf = 0; nf < 4; nf++) {
            const int kg = c * 64 + cdw + nf * 8 + 2 * t;
            const float e0 = eNs[kg];
            const float e1 = eNs[kg + 1];
#pragma unroll
            for (int mf = 0; mf < 2; mf++) {
                float d0 = fmaf(-2.f, acc[mf][nf][0], e0);
                float d1 = fmaf(-2.f, acc[mf][nf][1], e1);
                float d2 = fmaf(-2.f, acc[mf][nf][2], e0);
                float d3 = fmaf(-2.f, acc[mf][nf][3], e1);
                const int s0 = mf * 2, s1 = mf * 2 + 1;   // rows g+16mf, g+8+16mf
                if (d0 < best[s0]) { best[s0] = d0; bk[s0] = kg; }
                if (d1 < best[s0]) { best[s0] = d1; bk[s0] = kg + 1; }
                if (d2 < best[s1]) { best[s1] = d2; bk[s1] = kg; }
                if (d3 < best[s1]) { best[s1] = d3; bk[s1] = kg + 1; }
            }
        }
    }
    __syncthreads();

    // ---- merge across the 4 t-lanes of each quad (tie: smallest k)
#pragma unroll
    for (int s = 0; s < 4; s++) {
        float v = best[s]; int kk = bk[s];
#pragma unroll
        for (int off = 1; off <= 2; off <<= 1) {
            float ov = __shfl_xor_sync(0xFFFFFFFFu, v, off);
            int   ok = __shfl_xor_sync(0xFFFFFFFFu, kk, off);
            if (ov < v || (ov == v && ok < kk)) { v = ov; kk = ok; }
        }
        best[s] = v; bk[s] = kk;
    }

    // ---- merge warp pairs (cd halves) via smem, then write
    float* mb = (float*)sm2;            // 128 floats
    int*   mk = (int*)sm2 + 256;
    const int rowoff[4] = {g, 8 + g, 16 + g, 24 + g};
    if ((wid & 1) == 0 && t == 0) {
#pragma unroll
        for (int s = 0; s < 4; s++) { mb[ptb + rowoff[s]] = best[s]; mk[ptb + rowoff[s]] = bk[s]; }
    }
    __syncthreads();
    if ((wid & 1) == 1 && t == 0) {
#pragma unroll
        for (int s = 0; s < 4; s++) {
            const int row = ptb + rowoff[s];
            float ov = mb[row]; int ok = mk[row];
            float v = best[s]; int kk = bk[s];
            if (ov < v || (ov == v && ok < kk)) { v = ov; kk = ok; }
            const int o = (b * NN + n) * HWHW + hw0 + row;
            d_idxBuf[o] = kk;
            argmin_out[o] = (float)kk;
            atomicAdd(&d_counts[n * KK + kk], 1);
        }
    }
}

// ============================================================
// Kernel C: gather q, z_q, diff partials
// ============================================================
__global__ __launch_bounds__(256)
void epi_kernel(const float* __restrict__ x, float* __restrict__ zq) {
    __shared__ float qs[128 * 33];
    __shared__ float red[256];
    const int tid = threadIdx.x;
    const int hw0 = blockIdx.x * 32;
    const int b = blockIdx.y, n = blockIdx.z;
    const int lane = tid & 31, w = tid >> 5;

#pragma unroll
    for (int pp = 0; pp < 4; pp++) {
        const int pt = w * 4 + pp;
        const int k = d_idxBuf[(b * NN + n) * HWHW + hw0 + pt];
        const float4 v = *((const float4*)(d_embedT + ((size_t)(n * KK + k)) * DD) + lane);
        const int d = lane * 4;
        qs[(d + 0) * 33 + pt] = v.x;
        qs[(d + 1) * 33 + pt] = v.y;
        qs[(d + 2) * 33 + pt] = v.z;
        qs[(d + 3) * 33 + pt] = v.w;
    }
    __syncthreads();

    float lsum = 0.f;
    const int hw = tid & 31, dh = tid >> 5;
#pragma unroll
    for (int d0 = 0; d0 < 128; d0 += 8) {
        const int d = d0 + dh;
        const size_t off = ((size_t)b * CC + n * DD + d) * HWHW + hw0 + hw;
        const float xv = __ldg(x + off);
        const float t = qs[d * 33 + hw] - xv;
        zq[off] = xv + t;
        lsum = fmaf(t, t, lsum);
    }
    red[tid] = lsum;
    __syncthreads();
    for (int s = 128; s; s >>= 1) { if (tid < s) red[tid] += red[tid + s]; __syncthreads(); }
    if (tid == 0) d_diffPartial[(blockIdx.z * 64 + blockIdx.y) * 32 + blockIdx.x] = red[0];
}

// ============================================================
// Kernel D: final diff + ppl
// ============================================================
__global__ void final_kernel(float* __restrict__ out_diff, float* __restrict__ out_ppl) {
    __shared__ float red[1024];
    __shared__ float ent[NN];
    const int tid = threadIdx.x;
    float s = 0.f;
#pragma unroll
    for (int r = 0; r < 8; r++) s += d_diffPartial[r * 1024 + tid];
    red[tid] = s;
    __syncthreads();
    for (int st = 512; st; st >>= 1) { if (tid < st) red[tid] += red[tid + st]; __syncthreads(); }
    if (tid == 0) *out_diff = red[0] / 33554432.0f;
    __syncthreads();
    for (int n = 0; n < NN; n++) {
        const float p = (float)d_counts[n * KK + tid] * (1.0f / 65536.0f);
        red[tid] = p * logf(p + 1e-10f);
        __syncthreads();
        for (int st = 512; st; st >>= 1) { if (tid < st) red[tid] += red[tid + st]; __syncthreads(); }
        if (tid == 0) ent[n] = red[0];
        __syncthreads();
    }
    if (tid == 0) {
        float ppl = 0.f;
        for (int n = 0; n < NN; n++) ppl += expf(-ent[n]);
        *out_ppl = ppl * 0.25f;
    }
}

// ============================================================
extern "C" void kernel_launch(void* const* d_in, const int* in_sizes, int n_in,
                              void* d_out, int out_size) {
    const float* x     = (const float*)d_in[0];
    const float* embed = (const float*)d_in[1];
    if (in_sizes[0] == NN * DD * KK) { x = (const float*)d_in[1]; embed = (const float*)d_in[0]; }

    float* out = (float*)d_out;
    float* zq   = out;
    float* diff = out + 33554432;
    float* argm = out + 33554433;
    float* ppl  = out + 33554433 + 262144;

    cudaFuncSetAttribute(vq_mma, cudaFuncAttributeMaxDynamicSharedMemorySize, SM_TOTAL_B);

    prep_kernel<<<32, 128>>>(embed);
    vq_mma<<<dim3(512, 4), 256, SM_TOTAL_B>>>(x, argm);
    epi_kernel<<<dim3(32, 64, 4), 256>>>(x, zq);
    final_kernel<<<1, 1024>>>(diff, ppl);
}

// round 13
// speedup vs baseline: 1.1051x; 1.1051x over previous
#include <cuda_runtime.h>
#include <cstdint>

#define BB 64
#define CC 512
#define HWHW 1024
#define NN 4
#define DD 128
#define KK 1024
// P = 65536 points

// -------- scratch --------
__device__ __align__(16) float d_eNorm[NN * KK];
__device__ __align__(16) float d_embedT[(size_t)NN * KK * DD];   // fp32 [n][k][d] for epi gather
__device__ int   d_idxBuf[BB * NN * HWHW];
__device__ int   d_counts[NN * KK];
__device__ __align__(16) float d_diffPartial[8192];

__device__ __forceinline__ uint32_t f2tf32(float f) {
    uint32_t u;
    asm("cvt.rna.tf32.f32 %0, %1;" : "=r"(u) : "f"(f));
    return u;
}

// legacy warp-level tensor mma (sm_80+, plain target)
__device__ __forceinline__ void mma8(float* c, const uint32_t* a, uint32_t b0, uint32_t b1) {
    asm volatile(
        "mma.sync.aligned.m16n8k8.row.col.f32.tf32.tf32.f32 "
        "{%0,%1,%2,%3}, {%4,%5,%6,%7}, {%8,%9}, {%0,%1,%2,%3};"
        : "+f"(c[0]), "+f"(c[1]), "+f"(c[2]), "+f"(c[3])
        : "r"(a[0]), "r"(a[1]), "r"(a[2]), "r"(a[3]), "r"(b0), "r"(b1));
}

// monotonic float -> uint32 (order-preserving incl. negatives)
__device__ __forceinline__ uint32_t fmono(float f) {
    uint32_t b = __float_as_uint(f);
    return (b & 0x80000000u) ? ~b : (b | 0x80000000u);
}

// ============================================================
// Kernel A: eNorm + transposed codebook + zero counts
// ============================================================
__global__ void prep_kernel(const float* __restrict__ embed) {
    const int n  = blockIdx.x >> 3;
    const int kc = blockIdx.x & 7;
    const int k  = kc * 128 + threadIdx.x;
    const float* e = embed + (size_t)n * DD * KK + k;
    float* tB = d_embedT + ((size_t)(n * KK + k)) * DD;
    float s = 0.f;
#pragma unroll 8
    for (int d = 0; d < DD; d++) {
        float v = e[(size_t)d * KK];
        s = fmaf(v, v, s);
        tB[d] = v;
    }
    d_eNorm[n * KK + k] = s;
    d_counts[blockIdx.x * 128 + threadIdx.x] = 0;
}

// ============================================================
// Kernel B: tf32 3-split mma.sync distance GEMM + fused argmin
// grid (512, 4): 128 pt x 1024 codes/block, 512 thr (16 warps)
// warp grid 4(pt) x 4(cd); warp tile 32x32; chunk 128 codes (8 chunks)
// smem fp32 [k][m] stride 136 (R6-proven layout), in-loop cvt
// ============================================================
#define ZSTR 136
#define SM_ES    17408           // float offsets
#define SM_ENS   34816
#define SM_KEYS  34944           // u64[128] @ byte 139776 (8-aligned)
#define SM_BYTES 140800

__global__ __launch_bounds__(512, 1)
void vq_mma(const float* __restrict__ x, const float* __restrict__ embed,
            float* __restrict__ argmin_out) {
    extern __shared__ float sm[];
    float* zs  = sm;                 // [128 k][128 pt] stride 136
    float* es  = sm + SM_ES;         // [128 k][128 cd] stride 136
    float* eNs = sm + SM_ENS;        // [128]
    unsigned long long* keys = (unsigned long long*)(sm + SM_KEYS);  // [128]

    const int tid = threadIdx.x;
    const int wid = tid >> 5;
    const int lane = tid & 31;
    const int g = lane >> 2;             // 0..7
    const int t = lane & 3;              // 0..3
    const int b = blockIdx.x >> 3;
    const int hw0 = (blockIdx.x & 7) * 128;
    const int n = blockIdx.y;
    const int ptb = (wid >> 2) * 32;     // warp point base
    const int cdw = (wid & 3) * 32;      // warp code base within chunk

    // ---- stage z tile once: zs[d][pt] = x[b][n*128+d][hw0+pt]
    const float* xblk = x + ((size_t)b * CC + n * DD) * HWHW + hw0;
#pragma unroll
    for (int r = 0; r < 8; r++) {
        int l = r * 512 + tid;
        int d = l >> 5, q = l & 31;          // 32 float4 per 128-float row
        *(float4*)(zs + d * ZSTR + q * 4) = __ldg((const float4*)(xblk + (size_t)d * HWHW) + q);
    }
    if (tid < 128) keys[tid] = 0xFFFFFFFFFFFFFFFFull;

    float best[4] = {3.4e38f, 3.4e38f, 3.4e38f, 3.4e38f};
    int   bk[4]   = {0, 0, 0, 0};

    const float* eblk = embed + (size_t)n * DD * KK;

    for (int c = 0; c < 8; c++) {
        __syncthreads();     // prior chunk's reads done (covers zs/keys init on c=0)
        // ---- stage e chunk: es[d][cd] = embed[n][d][c*128+cd]
        const float* ebl = eblk + c * 128;
#pragma unroll
        for (int r = 0; r < 8; r++) {
            int l = r * 512 + tid;
            int d = l >> 5, q = l & 31;
            *(float4*)(es + d * ZSTR + q * 4) = __ldg((const float4*)(ebl + (size_t)d * KK) + q);
        }
        if (tid < 32)
            ((float4*)eNs)[tid] = __ldg((const float4*)(d_eNorm + n * KK + c * 128) + tid);
        __syncthreads();

        float acc[2][4][4];
#pragma unroll
        for (int mf = 0; mf < 2; mf++)
#pragma unroll
            for (int nf = 0; nf < 4; nf++)
#pragma unroll
                for (int i = 0; i < 4; i++) acc[mf][nf][i] = 0.f;

#pragma unroll 4
        for (int ks = 0; ks < 16; ks++) {
            // A fragments: rows ptb+{g,g+8}+16mf, cols k {t, t+4}
            const float* zr0 = zs + (ks * 8 + t) * ZSTR + ptb + g;
            const float* zr4 = zr0 + 4 * ZSTR;
            uint32_t ah[2][4], al[2][4];
#pragma unroll
            for (int mf = 0; mf < 2; mf++) {
                const int o = mf * 16;
                float v0 = zr0[o], v1 = zr0[o + 8], v2 = zr4[o], v3 = zr4[o + 8];
                ah[mf][0] = f2tf32(v0); al[mf][0] = f2tf32(v0 - __uint_as_float(ah[mf][0]));
                ah[mf][1] = f2tf32(v1); al[mf][1] = f2tf32(v1 - __uint_as_float(ah[mf][1]));
                ah[mf][2] = f2tf32(v2); al[mf][2] = f2tf32(v2 - __uint_as_float(ah[mf][2]));
                ah[mf][3] = f2tf32(v3); al[mf][3] = f2tf32(v3 - __uint_as_float(ah[mf][3]));
            }
            // B fragments: b0=(k t, cd g) b1=(k t+4, cd g)
            const float* er0 = es + (ks * 8 + t) * ZSTR + cdw + g;
            const float* er4 = er0 + 4 * ZSTR;
            uint32_t bh0[4], bl0[4], bh1[4], bl1[4];
#pragma unroll
            for (int nf = 0; nf < 4; nf++) {
                float q0 = er0[nf * 8], q1 = er4[nf * 8];
                bh0[nf] = f2tf32(q0); bl0[nf] = f2tf32(q0 - __uint_as_float(bh0[nf]));
                bh1[nf] = f2tf32(q1); bl1[nf] = f2tf32(q1 - __uint_as_float(bh1[nf]));
            }
            // term-outer issue: 8 independent accumulators per term
#pragma unroll
            for (int mf = 0; mf < 2; mf++)
#pragma unroll
                for (int nf = 0; nf < 4; nf++)
                    mma8(acc[mf][nf], ah[mf], bh0[nf], bh1[nf]);   // hi*hi
#pragma unroll
            for (int mf = 0; mf < 2; mf++)
#pragma unroll
                for (int nf = 0; nf < 4; nf++)
                    mma8(acc[mf][nf], al[mf], bh0[nf], bh1[nf]);   // lo*hi
#pragma unroll
            for (int mf = 0; mf < 2; mf++)
#pragma unroll
                for (int nf = 0; nf < 4; nf++)
                    mma8(acc[mf][nf], ah[mf], bl0[nf], bl1[nf]);   // hi*lo
        }

        // ---- fold chunk into running argmin
        // C frag: c0=(g,2t) c1=(g,2t+1) c2=(g+8,2t) c3=(g+8,2t+1); mf adds +16 rows
#pragma unroll
        for (int nf = 0; nf < 4; nf++) {
            const int kc_ = cdw + nf * 8 + 2 * t;
            const int kg = c * 128 + kc_;
            const float e0 = eNs[kc_];
            const float e1 = eNs[kc_ + 1];
#pragma unroll
            for (int mf = 0; mf < 2; mf++) {
                float d0 = fmaf(-2.f, acc[mf][nf][0], e0);
                float d1 = fmaf(-2.f, acc[mf][nf][1], e1);
                float d2 = fmaf(-2.f, acc[mf][nf][2], e0);
                float d3 = fmaf(-2.f, acc[mf][nf][3], e1);
                const int s0 = mf * 2, s1 = mf * 2 + 1;   // rows g+16mf, g+8+16mf
                if (d0 < best[s0]) { best[s0] = d0; bk[s0] = kg; }
                if (d1 < best[s0]) { best[s0] = d1; bk[s0] = kg + 1; }
                if (d2 < best[s1]) { best[s1] = d2; bk[s1] = kg; }
                if (d3 < best[s1]) { best[s1] = d3; bk[s1] = kg + 1; }
            }
        }
    }
    __syncthreads();

    // ---- merge across the 4 t-lanes of each quad (tie: smallest k)
#pragma unroll
    for (int s = 0; s < 4; s++) {
        float v = best[s]; int kk = bk[s];
#pragma unroll
        for (int off = 1; off <= 2; off <<= 1) {
            float ov = __shfl_xor_sync(0xFFFFFFFFu, v, off);
            int   ok = __shfl_xor_sync(0xFFFFFFFFu, kk, off);
            if (ov < v || (ov == v && ok < kk)) { v = ov; kk = ok; }
        }
        best[s] = v; bk[s] = kk;
    }

    // ---- cross-warp merge via monotonic (dist,k) atomicMin (lexicographic)
    if (t == 0) {
        const int rowoff[4] = {g, 8 + g, 16 + g, 24 + g};
#pragma unroll
        for (int s = 0; s < 4; s++) {
            unsigned long long key = ((unsigned long long)fmono(best[s]) << 32) | (uint32_t)bk[s];
            atomicMin(&keys[ptb + rowoff[s]], key);
        }
    }
    __syncthreads();

    if (tid < 128) {
        const int kk = (int)(uint32_t)keys[tid];
        const int o = (b * NN + n) * HWHW + hw0 + tid;
        d_idxBuf[o] = kk;
        argmin_out[o] = (float)kk;
        atomicAdd(&d_counts[n * KK + kk], 1);
    }
}

// ============================================================
// Kernel C: gather q, z_q, diff partials
// ============================================================
__global__ __launch_bounds__(256)
void epi_kernel(const float* __restrict__ x, float* __restrict__ zq) {
    __shared__ float qs[128 * 33];
    __shared__ float red[256];
    const int tid = threadIdx.x;
    const int hw0 = blockIdx.x * 32;
    const int b = blockIdx.y, n = blockIdx.z;
    const int lane = tid & 31, w = tid >> 5;

#pragma unroll
    for (int pp = 0; pp < 4; pp++) {
        const int pt = w * 4 + pp;
        const int k = d_idxBuf[(b * NN + n) * HWHW + hw0 + pt];
        const float4 v = *((const float4*)(d_embedT + ((size_t)(n * KK + k)) * DD) + lane);
        const int d = lane * 4;
        qs[(d + 0) * 33 + pt] = v.x;
        qs[(d + 1) * 33 + pt] = v.y;
        qs[(d + 2) * 33 + pt] = v.z;
        qs[(d + 3) * 33 + pt] = v.w;
    }
    __syncthreads();

    float lsum = 0.f;
    const int hw = tid & 31, dh = tid >> 5;
#pragma unroll
    for (int d0 = 0; d0 < 128; d0 += 8) {
        const int d = d0 + dh;
        const size_t off = ((size_t)b * CC + n * DD + d) * HWHW + hw0 + hw;
        const float xv = __ldg(x + off);
        const float t = qs[d * 33 + hw] - xv;
        zq[off] = xv + t;
        lsum = fmaf(t, t, lsum);
    }
    red[tid] = lsum;
    __syncthreads();
    for (int s = 128; s; s >>= 1) { if (tid < s) red[tid] += red[tid + s]; __syncthreads(); }
    if (tid == 0) d_diffPartial[(blockIdx.z * 64 + blockIdx.y) * 32 + blockIdx.x] = red[0];
}

// ============================================================
// Kernel D: final diff + ppl
// ============================================================
__global__ void final_kernel(float* __restrict__ out_diff, float* __restrict__ out_ppl) {
    __shared__ float red[1024];
    __shared__ float ent[NN];
    const int tid = threadIdx.x;
    float s = 0.f;
#pragma unroll
    for (int r = 0; r < 8; r++) s += d_diffPartial[r * 1024 + tid];
    red[tid] = s;
    __syncthreads();
    for (int st = 512; st; st >>= 1) { if (tid < st) red[tid] += red[tid + st]; __syncthreads(); }
    if (tid == 0) *out_diff = red[0] / 33554432.0f;
    __syncthreads();
    for (int n = 0; n < NN; n++) {
        const float p = (float)d_counts[n * KK + tid] * (1.0f / 65536.0f);
        red[tid] = p * logf(p + 1e-10f);
        __syncthreads();
        for (int st = 512; st; st >>= 1) { if (tid < st) red[tid] += red[tid + st]; __syncthreads(); }
        if (tid == 0) ent[n] = red[0];
        __syncthreads();
    }
    if (tid == 0) {
        float ppl = 0.f;
        for (int n = 0; n < NN; n++) ppl += expf(-ent[n]);
        *out_ppl = ppl * 0.25f;
    }
}

// ============================================================
extern "C" void kernel_launch(void* const* d_in, const int* in_sizes, int n_in,
                              void* d_out, int out_size) {
    const float* x     = (const float*)d_in[0];
    const float* embed = (const float*)d_in[1];
    if (in_sizes[0] == NN * DD * KK) { x = (const float*)d_in[1]; embed = (const float*)d_in[0]; }

    float* out = (float*)d_out;
    float* zq   = out;
    float* diff = out + 33554432;
    float* argm = out + 33554433;
    float* ppl  = out + 33554433 + 262144;

    cudaFuncSetAttribute(vq_mma, cudaFuncAttributeMaxDynamicSharedMemorySize, SM_BYTES);

    prep_kernel<<<32, 128>>>(embed);
    vq_mma<<<dim3(512, 4), 512, SM_BYTES>>>(x, embed, argm);
    epi_kernel<<<dim3(32, 64, 4), 256>>>(x, zq);
    final_kernel<<<1, 1024>>>(diff, ppl);
}

// round 14
// speedup vs baseline: 1.1287x; 1.0214x over previous
#include <cuda_runtime.h>
#include <cstdint>

#define BB 64
#define CC 512
#define HWHW 1024
#define NN 4
#define DD 128
#define KK 1024
// P = 65536 points

// -------- scratch --------
__device__ __align__(16) float d_eNorm[NN * KK];
__device__ __align__(16) float d_embedT[(size_t)NN * KK * DD];   // fp32 [n][k][d] for epi gather
__device__ int   d_idxBuf[BB * NN * HWHW];
__device__ int   d_counts[NN * KK];
__device__ __align__(16) float d_diffPartial[8192];

__device__ __forceinline__ uint32_t f2tf32(float f) {
    uint32_t u;
    asm("cvt.rna.tf32.f32 %0, %1;" : "=r"(u) : "f"(f));
    return u;
}

// legacy warp-level tensor mma (sm_80+, plain target)
__device__ __forceinline__ void mma8(float* c, const uint32_t* a, uint32_t b0, uint32_t b1) {
    asm volatile(
        "mma.sync.aligned.m16n8k8.row.col.f32.tf32.tf32.f32 "
        "{%0,%1,%2,%3}, {%4,%5,%6,%7}, {%8,%9}, {%0,%1,%2,%3};"
        : "+f"(c[0]), "+f"(c[1]), "+f"(c[2]), "+f"(c[3])
        : "r"(a[0]), "r"(a[1]), "r"(a[2]), "r"(a[3]), "r"(b0), "r"(b1));
}

// packed fp32x2 (FFMA2 path — IEEE-exact per lane)
__device__ __forceinline__ unsigned long long pk2(float lo, float hi) {
    unsigned long long r;
    asm("mov.b64 %0, {%1, %2};" : "=l"(r) : "f"(lo), "f"(hi));
    return r;
}
__device__ __forceinline__ void fma2(unsigned long long& d,
                                     unsigned long long a, unsigned long long b) {
    asm("fma.rn.f32x2 %0, %1, %2, %0;" : "+l"(d) : "l"(a), "l"(b));
}
__device__ __forceinline__ void unpk2(unsigned long long v, float& lo, float& hi) {
    asm("mov.b64 {%0, %1}, %2;" : "=f"(lo), "=f"(hi) : "l"(v));
}

// monotonic float -> uint32 (order-preserving)
__device__ __forceinline__ uint32_t fmono(float f) {
    uint32_t b = __float_as_uint(f);
    return (b & 0x80000000u) ? ~b : (b | 0x80000000u);
}

// ============================================================
// Kernel A: eNorm + transposed codebook + zero counts
// ============================================================
__global__ void prep_kernel(const float* __restrict__ embed) {
    const int n  = blockIdx.x >> 3;
    const int kc = blockIdx.x & 7;
    const int k  = kc * 128 + threadIdx.x;
    const float* e = embed + (size_t)n * DD * KK + k;
    float* tB = d_embedT + ((size_t)(n * KK + k)) * DD;
    float s = 0.f;
#pragma unroll 8
    for (int d = 0; d < DD; d++) {
        float v = e[(size_t)d * KK];
        s = fmaf(v, v, s);
        tB[d] = v;
    }
    d_eNorm[n * KK + k] = s;
    d_counts[blockIdx.x * 128 + threadIdx.x] = 0;
}

// ============================================================
// Kernel B: HYBRID tensor(tf32 3-split) + fma(FFMA2 fp32) GEMM+argmin
// grid (512, 4), 256 thr (8 warps): warps 0-3 tensor (cd 0-63 of chunk),
// warps 4-7 FFMA2 (cd 64-127). 8 chunks of 128 codes. Per SMSP: 1+1 warp.
// smem fp32 [k][m] stride 136 (R6-proven); keys u64 merge (R13-proven)
// ============================================================
#define ZSTR 136
#define SM_ES    17408           // float offsets
#define SM_ENS   34816
#define SM_KEYS  34944           // u64[128] @ byte 139776
#define SM_BYTES 140800

__global__ __launch_bounds__(256, 1)
void vq_hyb(const float* __restrict__ x, const float* __restrict__ embed,
            float* __restrict__ argmin_out) {
    extern __shared__ float sm[];
    float* zs  = sm;                 // [128 k][128 pt] stride 136
    float* es  = sm + SM_ES;         // [128 k][128 cd] stride 136
    float* eNs = sm + SM_ENS;        // [128]
    unsigned long long* keys = (unsigned long long*)(sm + SM_KEYS);  // [128]

    const int tid = threadIdx.x;
    const int wid = tid >> 5;
    const int lane = tid & 31;
    const int b = blockIdx.x >> 3;
    const int hw0 = (blockIdx.x & 7) * 128;
    const int n = blockIdx.y;

    // tensor-warp coords (wid 0-3)
    const int g = lane >> 2;             // 0..7
    const int t = lane & 3;              // 0..3
    const int ptb = wid * 32;            // tensor warp point base
    // fma-warp coords (wid 4-7)
    const int ftid = tid - 128;          // 0..127 (valid when wid>=4)
    const int fty = ftid >> 3;           // 0..15 -> pt rows fty*8..+8
    const int ftx = ftid & 7;            // 0..7  -> cd 64+ftx*8..+8

    // ---- stage z tile once: zs[d][pt] = x[b][n*128+d][hw0+pt]
    const float* xblk = x + ((size_t)b * CC + n * DD) * HWHW + hw0;
#pragma unroll
    for (int r = 0; r < 16; r++) {
        int l = r * 256 + tid;
        int d = l >> 5, q = l & 31;
        *(float4*)(zs + d * ZSTR + q * 4) = __ldg((const float4*)(xblk + (size_t)d * HWHW) + q);
    }
    if (tid < 128) keys[tid] = 0xFFFFFFFFFFFFFFFFull;

    // tensor-side running best (4 slots: rows g,8+g,16+g,24+g in warp tile)
    float tbest[4] = {3.4e38f, 3.4e38f, 3.4e38f, 3.4e38f};
    int   tbk[4]   = {0, 0, 0, 0};
    // fma-side running best (8 slots: pts fty*8+s)
    float fbest[8] = {3.4e38f, 3.4e38f, 3.4e38f, 3.4e38f, 3.4e38f, 3.4e38f, 3.4e38f, 3.4e38f};
    int   fbk[8]   = {0, 0, 0, 0, 0, 0, 0, 0};

    const float* eblk = embed + (size_t)n * DD * KK;

    for (int c = 0; c < 8; c++) {
        __syncthreads();     // prior chunk reads done (covers zs/keys on c=0)
        const float* ebl = eblk + c * 128;
#pragma unroll
        for (int r = 0; r < 16; r++) {
            int l = r * 256 + tid;
            int d = l >> 5, q = l & 31;
            *(float4*)(es + d * ZSTR + q * 4) = __ldg((const float4*)(ebl + (size_t)d * KK) + q);
        }
        if (tid < 32)
            ((float4*)eNs)[tid] = __ldg((const float4*)(d_eNorm + n * KK + c * 128) + tid);
        __syncthreads();

        if (wid < 4) {
            // ======== tensor half: codes 0..63 of chunk, 3-split tf32 ========
            float acc[2][8][4];
#pragma unroll
            for (int mf = 0; mf < 2; mf++)
#pragma unroll
                for (int nf = 0; nf < 8; nf++)
#pragma unroll
                    for (int i = 0; i < 4; i++) acc[mf][nf][i] = 0.f;

#pragma unroll 4
            for (int ks = 0; ks < 16; ks++) {
                const float* zr0 = zs + (ks * 8 + t) * ZSTR + ptb + g;
                const float* zr4 = zr0 + 4 * ZSTR;
                uint32_t ah[2][4], al[2][4];
#pragma unroll
                for (int mf = 0; mf < 2; mf++) {
                    const int o = mf * 16;
                    float v0 = zr0[o], v1 = zr0[o + 8], v2 = zr4[o], v3 = zr4[o + 8];
                    ah[mf][0] = f2tf32(v0); al[mf][0] = f2tf32(v0 - __uint_as_float(ah[mf][0]));
                    ah[mf][1] = f2tf32(v1); al[mf][1] = f2tf32(v1 - __uint_as_float(ah[mf][1]));
                    ah[mf][2] = f2tf32(v2); al[mf][2] = f2tf32(v2 - __uint_as_float(ah[mf][2]));
                    ah[mf][3] = f2tf32(v3); al[mf][3] = f2tf32(v3 - __uint_as_float(ah[mf][3]));
                }
                const float* er0 = es + (ks * 8 + t) * ZSTR + g;   // cdw = 0
                const float* er4 = er0 + 4 * ZSTR;
                uint32_t bh0[8], bl0[8], bh1[8], bl1[8];
#pragma unroll
                for (int nf = 0; nf < 8; nf++) {
                    float q0 = er0[nf * 8], q1 = er4[nf * 8];
                    bh0[nf] = f2tf32(q0); bl0[nf] = f2tf32(q0 - __uint_as_float(bh0[nf]));
                    bh1[nf] = f2tf32(q1); bl1[nf] = f2tf32(q1 - __uint_as_float(bh1[nf]));
                }
#pragma unroll
                for (int mf = 0; mf < 2; mf++)
#pragma unroll
                    for (int nf = 0; nf < 8; nf++)
                        mma8(acc[mf][nf], ah[mf], bh0[nf], bh1[nf]);   // hi*hi
#pragma unroll
                for (int mf = 0; mf < 2; mf++)
#pragma unroll
                    for (int nf = 0; nf < 8; nf++)
                        mma8(acc[mf][nf], al[mf], bh0[nf], bh1[nf]);   // lo*hi
#pragma unroll
                for (int mf = 0; mf < 2; mf++)
#pragma unroll
                    for (int nf = 0; nf < 8; nf++)
                        mma8(acc[mf][nf], ah[mf], bl0[nf], bl1[nf]);   // hi*lo
            }
            // fold: C frag c0=(g,2t) c1=(g,2t+1) c2=(g+8,2t) c3=(g+8,2t+1)
#pragma unroll
            for (int nf = 0; nf < 8; nf++) {
                const int kc_ = nf * 8 + 2 * t;
                const int kg = c * 128 + kc_;
                const float e0 = eNs[kc_];
                const float e1 = eNs[kc_ + 1];
#pragma unroll
                for (int mf = 0; mf < 2; mf++) {
                    float d0 = fmaf(-2.f, acc[mf][nf][0], e0);
                    float d1 = fmaf(-2.f, acc[mf][nf][1], e1);
                    float d2 = fmaf(-2.f, acc[mf][nf][2], e0);
                    float d3 = fmaf(-2.f, acc[mf][nf][3], e1);
                    const int s0 = mf * 2, s1 = mf * 2 + 1;
                    if (d0 < tbest[s0]) { tbest[s0] = d0; tbk[s0] = kg; }
                    if (d1 < tbest[s0]) { tbest[s0] = d1; tbk[s0] = kg + 1; }
                    if (d2 < tbest[s1]) { tbest[s1] = d2; tbk[s1] = kg; }
                    if (d3 < tbest[s1]) { tbest[s1] = d3; tbk[s1] = kg + 1; }
                }
            }
        } else {
            // ======== fma half: codes 64..127 of chunk, exact fp32 FFMA2 ========
            unsigned long long acc2[4][8];
#pragma unroll
            for (int i2 = 0; i2 < 4; i2++)
#pragma unroll
                for (int j = 0; j < 8; j++) acc2[i2][j] = pk2(0.f, 0.f);

#pragma unroll 8
            for (int d = 0; d < 128; d++) {
                const ulonglong2 zA = *(const ulonglong2*)(zs + d * ZSTR + fty * 8);
                const ulonglong2 zB = *(const ulonglong2*)(zs + d * ZSTR + fty * 8 + 4);
                const unsigned long long zp[4] = {zA.x, zA.y, zB.x, zB.y};
                const float4 e0 = *(const float4*)(es + d * ZSTR + 64 + ftx * 8);
                const float4 e1 = *(const float4*)(es + d * ZSTR + 64 + ftx * 8 + 4);
                unsigned long long ep[8];
                ep[0] = pk2(e0.x, e0.x); ep[1] = pk2(e0.y, e0.y);
                ep[2] = pk2(e0.z, e0.z); ep[3] = pk2(e0.w, e0.w);
                ep[4] = pk2(e1.x, e1.x); ep[5] = pk2(e1.y, e1.y);
                ep[6] = pk2(e1.z, e1.z); ep[7] = pk2(e1.w, e1.w);
#pragma unroll
                for (int j = 0; j < 8; j++)
#pragma unroll
                    for (int i2 = 0; i2 < 4; i2++)
                        fma2(acc2[i2][j], zp[i2], ep[j]);
            }
            // fold
#pragma unroll
            for (int j = 0; j < 8; j++) {
                const int kc_ = 64 + ftx * 8 + j;
                const int kg = c * 128 + kc_;
                const float en = eNs[kc_];
#pragma unroll
                for (int i2 = 0; i2 < 4; i2++) {
                    float alo, ahi;
                    unpk2(acc2[i2][j], alo, ahi);
                    float vlo = fmaf(-2.f, alo, en);
                    float vhi = fmaf(-2.f, ahi, en);
                    if (vlo < fbest[2 * i2])     { fbest[2 * i2] = vlo;     fbk[2 * i2] = kg; }
                    if (vhi < fbest[2 * i2 + 1]) { fbest[2 * i2 + 1] = vhi; fbk[2 * i2 + 1] = kg; }
                }
            }
        }
    }
    __syncthreads();

    // ---- merges (all lexicographic (dist,k) -> jnp tie-break)
    if (wid < 4) {
#pragma unroll
        for (int s = 0; s < 4; s++) {
            float v = tbest[s]; int kk = tbk[s];
#pragma unroll
            for (int off = 1; off <= 2; off <<= 1) {
                float ov = __shfl_xor_sync(0xFFFFFFFFu, v, off);
                int   ok = __shfl_xor_sync(0xFFFFFFFFu, kk, off);
                if (ov < v || (ov == v && ok < kk)) { v = ov; kk = ok; }
            }
            if (t == 0) {
                const int row = ptb + ((s & 1) ? 8 : 0) + ((s & 2) ? 16 : 0) + g;
                unsigned long long key = ((unsigned long long)fmono(v) << 32) | (uint32_t)kk;
                atomicMin(&keys[row], key);
            }
        }
    } else {
#pragma unroll
        for (int s = 0; s < 8; s++) {
            unsigned long long key = ((unsigned long long)fmono(fbest[s]) << 32) | (uint32_t)fbk[s];
            atomicMin(&keys[fty * 8 + s], key);
        }
    }
    __syncthreads();

    if (tid < 128) {
        const int kk = (int)(uint32_t)keys[tid];
        const int o = (b * NN + n) * HWHW + hw0 + tid;
        d_idxBuf[o] = kk;
        argmin_out[o] = (float)kk;
        atomicAdd(&d_counts[n * KK + kk], 1);
    }
}

// ============================================================
// Kernel C: gather q, z_q, diff partials
// ============================================================
__global__ __launch_bounds__(256)
void epi_kernel(const float* __restrict__ x, float* __restrict__ zq) {
    __shared__ float qs[128 * 33];
    __shared__ float red[256];
    const int tid = threadIdx.x;
    const int hw0 = blockIdx.x * 32;
    const int b = blockIdx.y, n = blockIdx.z;
    const int lane = tid & 31, w = tid >> 5;

#pragma unroll
    for (int pp = 0; pp < 4; pp++) {
        const int pt = w * 4 + pp;
        const int k = d_idxBuf[(b * NN + n) * HWHW + hw0 + pt];
        const float4 v = *((const float4*)(d_embedT + ((size_t)(n * KK + k)) * DD) + lane);
        const int d = lane * 4;
        qs[(d + 0) * 33 + pt] = v.x;
        qs[(d + 1) * 33 + pt] = v.y;
        qs[(d + 2) * 33 + pt] = v.z;
        qs[(d + 3) * 33 + pt] = v.w;
    }
    __syncthreads();

    float lsum = 0.f;
    const int hw = tid & 31, dh = tid >> 5;
#pragma unroll
    for (int d0 = 0; d0 < 128; d0 += 8) {
        const int d = d0 + dh;
        const size_t off = ((size_t)b * CC + n * DD + d) * HWHW + hw0 + hw;
        const float xv = __ldg(x + off);
        const float t = qs[d * 33 + hw] - xv;
        zq[off] = xv + t;
        lsum = fmaf(t, t, lsum);
    }
    red[tid] = lsum;
    __syncthreads();
    for (int s = 128; s; s >>= 1) { if (tid < s) red[tid] += red[tid + s]; __syncthreads(); }
    if (tid == 0) d_diffPartial[(blockIdx.z * 64 + blockIdx.y) * 32 + blockIdx.x] = red[0];
}

// ============================================================
// Kernel D: final diff + ppl
// ============================================================
__global__ void final_kernel(float* __restrict__ out_diff, float* __restrict__ out_ppl) {
    __shared__ float red[1024];
    __shared__ float ent[NN];
    const int tid = threadIdx.x;
    float s = 0.f;
#pragma unroll
    for (int r = 0; r < 8; r++) s += d_diffPartial[r * 1024 + tid];
    red[tid] = s;
    __syncthreads();
    for (int st = 512; st; st >>= 1) { if (tid < st) red[tid] += red[tid + st]; __syncthreads(); }
    if (tid == 0) *out_diff = red[0] / 33554432.0f;
    __syncthreads();
    for (int n = 0; n < NN; n++) {
        const float p = (float)d_counts[n * KK + tid] * (1.0f / 65536.0f);
        red[tid] = p * logf(p + 1e-10f);
        __syncthreads();
        for (int st = 512; st; st >>= 1) { if (tid < st) red[tid] += red[tid + st]; __syncthreads(); }
        if (tid == 0) ent[n] = red[0];
        __syncthreads();
    }
    if (tid == 0) {
        float ppl = 0.f;
        for (int n = 0; n < NN; n++) ppl += expf(-ent[n]);
        *out_ppl = ppl * 0.25f;
    }
}

// ============================================================
extern "C" void kernel_launch(void* const* d_in, const int* in_sizes, int n_in,
                              void* d_out, int out_size) {
    const float* x     = (const float*)d_in[0];
    const float* embed = (const float*)d_in[1];
    if (in_sizes[0] == NN * DD * KK) { x = (const float*)d_in[1]; embed = (const float*)d_in[0]; }

    float* out = (float*)d_out;
    float* zq   = out;
    float* diff = out + 33554432;
    float* argm = out + 33554433;
    float* ppl  = out + 33554433 + 262144;

    cudaFuncSetAttribute(vq_hyb, cudaFuncAttributeMaxDynamicSharedMemorySize, SM_BYTES);

    prep_kernel<<<32, 128>>>(embed);
    vq_hyb<<<dim3(512, 4), 256, SM_BYTES>>>(x, embed, argm);
    epi_kernel<<<dim3(32, 64, 4), 256>>>(x, zq);
    final_kernel<<<1, 1024>>>(diff, ppl);
}